// round 3
// baseline (speedup 1.0000x reference)
#include <cuda_runtime.h>
#include <stdint.h>

#define D 256
#define BQ 1024
#define KTOP 1024
#define MMAX 100000
#define CAND_MAX 4096
#define FEAT_BLOCKS 128
#define NBINS 65536   // 16-bit single-level radix select

// ---------------- static device scratch ----------------
__device__ float g_pfsum[FEAT_BLOCKS][D];
__device__ float g_fsum[D];
__device__ unsigned long long g_keys[MMAX];
__device__ int g_hist[NBINS];          // 256 KB
__device__ int g_Tbin;                 // threshold bin (bin >= T are candidates)
__device__ unsigned long long g_cand[CAND_MAX];
__device__ int g_ncand;
__device__ int g_topidx[KTOP];

// ---------------- K0: zero histogram + counters ----------------
__global__ void k_zero() {
    int i = blockIdx.x * blockDim.x + threadIdx.x;   // 64K threads
    g_hist[i] = 0;
    if (i == 0) g_ncand = 0;
}

// ---------------- K1: per-block partial feature sums (deterministic) ----------------
__global__ void k_feat1(const float* __restrict__ f) {
    const int RPB = BQ / FEAT_BLOCKS;  // 8 rows per block
    int blk = blockIdx.x;
    int d = threadIdx.x;               // 256 threads, one per dim
    float s = 0.f;
    int base = blk * RPB * D + d;
#pragma unroll
    for (int r = 0; r < RPB; r++) s += f[base + r * D];
    g_pfsum[blk][d] = s;
}

// ---------------- K1b: final feature reduction ----------------
__global__ void k_feat2() {
    int d = threadIdx.x;  // 256
    float s = 0.f;
#pragma unroll 8
    for (int b = 0; b < FEAT_BLOCKS; b++) s += g_pfsum[b][d];
    g_fsum[d] = s;
}

// ---------------- K2: scores + sortable keys + 16-bit histogram ----------------
// Warp processes 4 rows; 8 independent float4 loads in flight per thread.
__global__ void k_scores(const float* __restrict__ mem, int M) {
    __shared__ __align__(16) float sf[D];   // holds -2 * fsum
    int tid = threadIdx.x;
    sf[tid] = -2.f * g_fsum[tid];
    __syncthreads();

    int warp = tid >> 5, lane = tid & 31;
    int base_row = (blockIdx.x * 8 + warp) * 4;
    if (base_row >= M) return;

    const float4* f4 = (const float4*)sf;
    float4 fa = f4[lane * 2], fb = f4[lane * 2 + 1];

    float4 A[4], Bv[4];
#pragma unroll
    for (int r = 0; r < 4; r++) {
        int row = base_row + r;
        if (row >= M) row = M - 1;  // safe duplicate; discarded below
        const float4* m4 = (const float4*)(mem + (size_t)row * D);
        A[r]  = m4[lane * 2];
        Bv[r] = m4[lane * 2 + 1];
    }

    const float Bf = (float)BQ;
    float acc[4];
#pragma unroll
    for (int r = 0; r < 4; r++) {
        float4 a = A[r], b = Bv[r];
        acc[r] = a.x * (Bf * a.x + fa.x)
               + a.y * (Bf * a.y + fa.y)
               + a.z * (Bf * a.z + fa.z)
               + a.w * (Bf * a.w + fa.w)
               + b.x * (Bf * b.x + fb.x)
               + b.y * (Bf * b.y + fb.y)
               + b.z * (Bf * b.z + fb.z)
               + b.w * (Bf * b.w + fb.w);
    }
#pragma unroll
    for (int o = 16; o > 0; o >>= 1) {
#pragma unroll
        for (int r = 0; r < 4; r++)
            acc[r] += __shfl_xor_sync(0xffffffffu, acc[r], o);
    }

    if (lane < 4) {
        int row = base_row + lane;
        if (row < M) {
            float v = lane == 0 ? acc[0] : lane == 1 ? acc[1] : lane == 2 ? acc[2] : acc[3];
            float score = -v;   // constants (f_sq) are rank-invariant; dropped
            unsigned u = __float_as_uint(score);
            u = (u & 0x80000000u) ? ~u : (u | 0x80000000u);  // monotone map
            unsigned long long key =
                ((unsigned long long)u << 32) | (unsigned)(~row);  // smaller row wins ties
            g_keys[row] = key;
            atomicAdd(&g_hist[u >> 16], 1);
        }
    }
}

// ---------------- K3: fused threshold: per-thread sums + shfl suffix scan ----------------
__global__ void k_thresh() {
    __shared__ int ssuf[1024];
    __shared__ int warpsum[32];
    int t = threadIdx.x;          // 1024
    int lane = t & 31, w = t >> 5;

    // sum my 64 bins (bins [t*64, t*64+64))
    int s = 0;
    const int4* h4 = (const int4*)(g_hist + t * 64);
#pragma unroll
    for (int i = 0; i < 16; i++) { int4 v = h4[i]; s += v.x + v.y + v.z + v.w; }

    // warp-level inclusive suffix sum
    int v = s;
#pragma unroll
    for (int off = 1; off < 32; off <<= 1) {
        int u = __shfl_down_sync(0xffffffffu, v, off);
        if (lane + off < 32) v += u;
    }
    if (lane == 0) warpsum[w] = v;       // warp totals
    __syncthreads();
    if (t < 32) {
        int wv = warpsum[t];
#pragma unroll
        for (int off = 1; off < 32; off <<= 1) {
            int u = __shfl_down_sync(0xffffffffu, wv, off);
            if (t + off < 32) wv += u;
        }
        warpsum[t] = wv;                 // inclusive suffix over warps
    }
    __syncthreads();
    int suf = v + ((w < 31) ? warpsum[w + 1] : 0);  // inclusive suffix from thread t
    ssuf[t] = suf;
    __syncthreads();

    if (suf >= KTOP && (t == 1023 || ssuf[t + 1] < KTOP)) {
        // boundary bin lies inside my 64-bin range
        int cum = (t == 1023) ? 0 : ssuf[t + 1];
        int b;
        for (b = t * 64 + 63; b >= t * 64; b--) {
            cum += g_hist[b];
            if (cum >= KTOP) break;
        }
        g_Tbin = b;
    }
}

// ---------------- K4: collect candidates ----------------
__global__ void k_collect(int M) {
    int i = blockIdx.x * blockDim.x + threadIdx.x;
    if (i >= M) return;
    unsigned long long key = g_keys[i];
    int bin = (int)(key >> 48);
    if (bin >= g_Tbin) {
        int p = atomicAdd(&g_ncand, 1);
        if (p < CAND_MAX) g_cand[p] = key;
    }
}

// ---------------- K5: exact rank by counting (keys unique -> ranks unique) ----------------
__global__ void k_rank() {
    __shared__ unsigned long long sk[CAND_MAX];  // 32 KB
    int t = threadIdx.x;                          // 1024
    int n = g_ncand;
    if (n > CAND_MAX) n = CAND_MAX;
    int npad = (n + 3) & ~3;

    for (int j = t; j < n; j += 1024) sk[j] = g_cand[j];
    if (n + t < npad) sk[n + t] = 0ULL;  // pad: smaller than any real key
    __syncthreads();

    int i = blockIdx.x * 1024 + t;
    if (i < n) {
        unsigned long long me = sk[i];
        int cnt = 0;
        for (int j = 0; j < npad; j += 4) {
            cnt += (sk[j]     > me);
            cnt += (sk[j + 1] > me);
            cnt += (sk[j + 2] > me);
            cnt += (sk[j + 3] > me);
        }
        if (cnt < KTOP) g_topidx[cnt] = (int)(~(unsigned)me);
    }
}

// ---------------- K6: gather winning rows ----------------
__global__ void k_gather(const float* __restrict__ mem, float* __restrict__ out) {
    int r = blockIdx.x * 2 + (threadIdx.x >> 6);  // 2 rows per block
    int t = threadIdx.x & 63;
    int idx = g_topidx[r];
    const float4* src = (const float4*)(mem + (size_t)idx * D);
    float4* dst = (float4*)(out + (size_t)r * D);
    dst[t] = src[t];
}

extern "C" void kernel_launch(void* const* d_in, const int* in_sizes, int n_in,
                              void* d_out, int out_size) {
    const float* p0 = (const float*)d_in[0];
    const float* p1 = (const float*)d_in[1];
    const float* feat;
    const float* mem;
    int M;
    if (in_sizes[0] <= in_sizes[1]) { feat = p0; mem = p1; M = in_sizes[1] / D; }
    else                            { feat = p1; mem = p0; M = in_sizes[0] / D; }

    k_zero<<<NBINS / 256, 256>>>();
    k_feat1<<<FEAT_BLOCKS, 256>>>(feat);
    k_feat2<<<1, 256>>>();
    k_scores<<<(M + 31) / 32, 256>>>(mem, M);
    k_thresh<<<1, 1024>>>();
    k_collect<<<(M + 255) / 256, 256>>>(M);
    k_rank<<<CAND_MAX / 1024, 1024>>>();
    k_gather<<<KTOP / 2, 128>>>(mem, (float*)d_out);
}

// round 4
// speedup vs baseline: 1.7328x; 1.7328x over previous
#include <cuda_runtime.h>
#include <stdint.h>

#define D 256
#define BQ 1024
#define KTOP 1024
#define MMAX 100000
#define CAND_MAX 4096
#define FEAT_BLOCKS 128
#define NBINS (1 << 20)   // 20-bit single-level radix select (low atomic contention)
#define NCHUNK 1024

// ---------------- static device scratch ----------------
__device__ float g_pfsum[FEAT_BLOCKS][D];
__device__ float g_fsum[D];
__device__ unsigned long long g_keys[MMAX];
__device__ int g_hist[NBINS];          // 4 MB
__device__ int g_chunk[NCHUNK];
__device__ int g_Tbin;
__device__ unsigned long long g_cand[CAND_MAX];
__device__ int g_ncand;
__device__ int g_topidx[KTOP];

// ---------------- K0: fused zero-hist + feature partial sums ----------------
// blocks [0, FEAT_BLOCKS): feature partials; blocks [FEAT_BLOCKS, +1024): zero hist
__global__ void k_init(const float* __restrict__ f) {
    int blk = blockIdx.x;
    int t = threadIdx.x;  // 256
    if (blk < FEAT_BLOCKS) {
        const int RPB = BQ / FEAT_BLOCKS;  // 8 rows per block
        float s = 0.f;
        int base = blk * RPB * D + t;
#pragma unroll
        for (int r = 0; r < RPB; r++) s += f[base + r * D];
        g_pfsum[blk][t] = s;
        if (blk == 0 && t == 0) g_ncand = 0;
    } else {
        int c = blk - FEAT_BLOCKS;        // 1024 blocks, 1024 ints each
        ((int4*)g_hist)[c * 256 + t] = make_int4(0, 0, 0, 0);
    }
}

// ---------------- K1: final feature reduction ----------------
__global__ void k_feat2() {
    int d = threadIdx.x;  // 256
    float s = 0.f;
#pragma unroll 8
    for (int b = 0; b < FEAT_BLOCKS; b++) s += g_pfsum[b][d];
    g_fsum[d] = -2.f * s;   // fold -2 here
}

// ---------------- K2: scores + sortable keys + 20-bit histogram ----------------
__global__ void k_scores(const float* __restrict__ mem, int M) {
    __shared__ __align__(16) float sf[D];
    int tid = threadIdx.x;
    sf[tid] = g_fsum[tid];
    __syncthreads();

    int warp = tid >> 5, lane = tid & 31;
    int base_row = (blockIdx.x * 8 + warp) * 4;
    if (base_row >= M) return;

    const float4* f4 = (const float4*)sf;
    float4 fa = f4[lane * 2], fb = f4[lane * 2 + 1];

    float4 A[4], Bv[4];
#pragma unroll
    for (int r = 0; r < 4; r++) {
        int row = base_row + r;
        if (row >= M) row = M - 1;
        const float4* m4 = (const float4*)(mem + (size_t)row * D);
        A[r]  = m4[lane * 2];
        Bv[r] = m4[lane * 2 + 1];
    }

    const float Bf = (float)BQ;
    float acc[4];
#pragma unroll
    for (int r = 0; r < 4; r++) {
        float4 a = A[r], b = Bv[r];
        acc[r] = a.x * (Bf * a.x + fa.x)
               + a.y * (Bf * a.y + fa.y)
               + a.z * (Bf * a.z + fa.z)
               + a.w * (Bf * a.w + fa.w)
               + b.x * (Bf * b.x + fb.x)
               + b.y * (Bf * b.y + fb.y)
               + b.z * (Bf * b.z + fb.z)
               + b.w * (Bf * b.w + fb.w);
    }
#pragma unroll
    for (int o = 16; o > 0; o >>= 1) {
#pragma unroll
        for (int r = 0; r < 4; r++)
            acc[r] += __shfl_xor_sync(0xffffffffu, acc[r], o);
    }

    if (lane < 4) {
        int row = base_row + lane;
        if (row < M) {
            float v = lane == 0 ? acc[0] : lane == 1 ? acc[1] : lane == 2 ? acc[2] : acc[3];
            float score = -v;
            unsigned u = __float_as_uint(score);
            u = (u & 0x80000000u) ? ~u : (u | 0x80000000u);
            unsigned long long key =
                ((unsigned long long)u << 32) | (unsigned)(~row);
            g_keys[row] = key;
            atomicAdd(&g_hist[u >> 12], 1);   // 20-bit: hot-bin occupancy ~100
        }
    }
}

// ---------------- K3: chunk sums over 1M bins ----------------
__global__ void k_chunksum() {
    __shared__ int red[256];
    int c = blockIdx.x;       // 1024 chunks of 1024 bins
    int t = threadIdx.x;      // 256 threads, 4 bins each
    const int4* h4 = (const int4*)(g_hist + c * 1024);
    int4 v = h4[t];
    red[t] = v.x + v.y + v.z + v.w;
    __syncthreads();
    for (int st = 128; st > 0; st >>= 1) {
        if (t < st) red[t] += red[t + st];
        __syncthreads();
    }
    if (t == 0) g_chunk[c] = red[0];
}

// Inclusive suffix-sum over 1024 values held one-per-thread (shfl, 2 levels).
__device__ __forceinline__ int suffix1024(int s, int t, int lane, int w, int* warpsum) {
    int v = s;
#pragma unroll
    for (int off = 1; off < 32; off <<= 1) {
        int u = __shfl_down_sync(0xffffffffu, v, off);
        if (lane + off < 32) v += u;
    }
    if (lane == 0) warpsum[w] = v;
    __syncthreads();
    if (t < 32) {
        int wv = warpsum[t];
#pragma unroll
        for (int off = 1; off < 32; off <<= 1) {
            int u = __shfl_down_sync(0xffffffffu, wv, off);
            if (t + off < 32) wv += u;
        }
        warpsum[t] = wv;
    }
    __syncthreads();
    return v + ((w < 31) ? warpsum[w + 1] : 0);
}

// ---------------- K4: threshold — all-parallel, no serial global chains ----------------
__global__ void k_thresh() {
    __shared__ int ssuf[NCHUNK];
    __shared__ int warpsum[32];
    __shared__ int sC, sCum;
    int t = threadIdx.x;  // 1024
    int lane = t & 31, w = t >> 5;

    // level 1: over chunk sums
    int suf = suffix1024(g_chunk[t], t, lane, w, warpsum);
    ssuf[t] = suf;
    __syncthreads();
    if (suf >= KTOP && (t == NCHUNK - 1 || ssuf[t + 1] < KTOP)) {
        sC = t;
        sCum = (t == NCHUNK - 1) ? 0 : ssuf[t + 1];  // count strictly above chunk
    }
    __syncthreads();
    int C = sC, cumAbove = sCum;
    __syncthreads();

    // level 2: parallel refine inside chunk C (one global load per thread)
    int suf2 = suffix1024(g_hist[C * 1024 + t], t, lane, w, warpsum);
    ssuf[t] = suf2;
    __syncthreads();
    if (cumAbove + suf2 >= KTOP &&
        (t == NCHUNK - 1 || cumAbove + ssuf[t + 1] < KTOP)) {
        g_Tbin = C * 1024 + t;
    }
}

// ---------------- K5: collect candidates ----------------
__global__ void k_collect(int M) {
    int i = blockIdx.x * blockDim.x + threadIdx.x;
    if (i >= M) return;
    unsigned long long key = g_keys[i];
    int bin = (int)(key >> 44);
    if (bin >= g_Tbin) {
        int p = atomicAdd(&g_ncand, 1);
        if (p < CAND_MAX) g_cand[p] = key;
    }
}

// ---------------- K6: exact rank by counting (keys unique) ----------------
__global__ void k_rank() {
    __shared__ unsigned long long sk[CAND_MAX];  // 32 KB
    int t = threadIdx.x;                          // 1024
    int n = g_ncand;
    if (n > CAND_MAX) n = CAND_MAX;
    int npad = (n + 3) & ~3;

    for (int j = t; j < n; j += 1024) sk[j] = g_cand[j];
    if (n + t < npad) sk[n + t] = 0ULL;
    __syncthreads();

    int i = blockIdx.x * 1024 + t;
    if (i < n) {
        unsigned long long me = sk[i];
        int cnt = 0;
        for (int j = 0; j < npad; j += 4) {
            cnt += (sk[j]     > me);
            cnt += (sk[j + 1] > me);
            cnt += (sk[j + 2] > me);
            cnt += (sk[j + 3] > me);
        }
        if (cnt < KTOP) g_topidx[cnt] = (int)(~(unsigned)me);
    }
}

// ---------------- K7: gather winning rows ----------------
__global__ void k_gather(const float* __restrict__ mem, float* __restrict__ out) {
    int r = blockIdx.x * 4 + (threadIdx.x >> 6);  // 4 rows per block
    int t = threadIdx.x & 63;
    int idx = g_topidx[r];
    const float4* src = (const float4*)(mem + (size_t)idx * D);
    float4* dst = (float4*)(out + (size_t)r * D);
    dst[t] = src[t];
}

extern "C" void kernel_launch(void* const* d_in, const int* in_sizes, int n_in,
                              void* d_out, int out_size) {
    const float* p0 = (const float*)d_in[0];
    const float* p1 = (const float*)d_in[1];
    const float* feat;
    const float* mem;
    int M;
    if (in_sizes[0] <= in_sizes[1]) { feat = p0; mem = p1; M = in_sizes[1] / D; }
    else                            { feat = p1; mem = p0; M = in_sizes[0] / D; }

    k_init<<<FEAT_BLOCKS + NBINS / 1024, 256>>>(feat);
    k_feat2<<<1, 256>>>();
    k_scores<<<(M + 31) / 32, 256>>>(mem, M);
    k_chunksum<<<NCHUNK, 256>>>();
    k_thresh<<<1, 1024>>>();
    k_collect<<<(M + 255) / 256, 256>>>(M);
    k_rank<<<CAND_MAX / 1024, 1024>>>();
    k_gather<<<KTOP / 4, 256>>>(mem, (float*)d_out);
}